// round 15
// baseline (speedup 1.0000x reference)
#include <cuda_runtime.h>
#include <cstdint>

#define NUM_EXPERTS 8
#define HIDDEN 2048
#define EXPERT_DIM 4096
#define TOKENS 1024

// Gated activations scratch [E, T, I] as fp16x2 words (proven rounds 9-13)
__device__ uint32_t Gh32[(size_t)NUM_EXPERTS * TOKENS * (EXPERT_DIM / 2)];

__device__ __forceinline__ uint32_t pack_h2(float a, float b) {
    uint32_t r;
    asm("cvt.rn.f16x2.f32 %0, %1, %2;" : "=r"(r) : "f"(b), "f"(a));
    return r;
}

__device__ __forceinline__ uint32_t smem_u32(const void* p) {
    uint32_t a;
    asm("{ .reg .u64 t; cvta.to.shared.u64 t, %1; cvt.u32.u64 %0, t; }" : "=r"(a) : "l"(p));
    return a;
}

__device__ __forceinline__ void ldsm_x4(uint32_t& r0, uint32_t& r1, uint32_t& r2,
                                        uint32_t& r3, uint32_t addr) {
    asm volatile("ldmatrix.sync.aligned.m8n8.x4.shared.b16 {%0,%1,%2,%3}, [%4];"
                 : "=r"(r0), "=r"(r1), "=r"(r2), "=r"(r3) : "r"(addr));
}

__device__ __forceinline__ void mma_f16(float* c, const uint32_t* a, const uint32_t* b) {
    asm volatile(
        "mma.sync.aligned.m16n8k16.row.col.f32.f16.f16.f32 "
        "{%0,%1,%2,%3}, {%4,%5,%6,%7}, {%8,%9}, {%0,%1,%2,%3};\n"
        : "+f"(c[0]), "+f"(c[1]), "+f"(c[2]), "+f"(c[3])
        : "r"(a[0]), "r"(a[1]), "r"(a[2]), "r"(a[3]), "r"(b[0]), "r"(b[1]));
}

// Rows of 16 k-pair words (BK=32) padded to 20 (proven). 20r mod 32 =
// {0,20,8,28,16,4,24,12} -> every 8-row ldmatrix phase and every 8-lane
// STS.128 phase covers all 32 banks.
#define R_ST 20
#define BUF_BYTES (128 * R_ST * 4)   // 10240

// ---------------------------------------------------------------------------
// GEMM1 + silu. Block: 128 tokens x 64 gated cols. K=2048, BK=32 (nT=64).
// 8 warps = 4(M) x 2(N). Warp tile 32x32 dual. 2 CTAs/SM. Plain layout,
// ldmatrix fragment loads, 16B B staging stores.
// ---------------------------------------------------------------------------
__global__ __launch_bounds__(256, 2) void gemm1_kernel(
    const float* __restrict__ X,    // [E*T, H]
    const float* __restrict__ W1)   // [E, H, 2I]
{
    __shared__ uint32_t As[2][128][R_ST];
    __shared__ uint32_t Bs[2][128][R_ST];

    const int e  = blockIdx.z;
    const int m0 = blockIdx.y * 128;
    const int n0 = blockIdx.x * 64;

    const int tid  = threadIdx.x;
    const int warp = tid >> 5;
    const int lane = tid & 31;
    const int wm = (warp >> 1) * 32;   // 4 warps in M
    const int wn = (warp & 1) * 32;    // 2 warps in N
    const int g  = lane >> 2;
    const int tg = lane & 3;

    const float* Ap = X + (size_t)(e * TOKENS + m0) * HIDDEN;
    const float* Bp = W1 + (size_t)e * HIDDEN * (2 * EXPERT_DIM);
    const int LDB = 2 * EXPERT_DIM;

    // ldmatrix lane address components
    const int a_lrow = lane & 15;
    const int a_lch  = (lane & 16) ? 4 : 0;
    const int b_lcol = (lane & 7) + ((lane & 16) ? 8 : 0);
    const int b_lch  = (lane & 8) ? 4 : 0;
    const uint32_t As0 = smem_u32(&As[0][0][0]);
    const uint32_t Bs0 = smem_u32(&Bs[0][0][0]);

    // A staging (round-13 proven): rows a_row + 32i, words 2a_u..2a_u+1
    const int a_row = tid >> 3;        // 0..31
    const int a_u   = tid & 7;
    // B staging: n fixed per thread, chunks {c0, c0+2}
    const int bn  = tid & 127;
    const int bc0 = tid >> 7;          // 0..1
    const int gcol = n0 + (bn < 64 ? bn : 4096 + (bn - 64));

    float4 ra[4];
    float fb[2][8];

    // prologue: stage tile 0
    {
        #pragma unroll
        for (int i = 0; i < 4; ++i) {
            const int row = a_row + i * 32;
            float4 v = *(const float4*)(Ap + (size_t)row * HIDDEN + a_u * 4);
            *(uint2*)&As[0][row][a_u * 2] = make_uint2(pack_h2(v.x, v.y), pack_h2(v.z, v.w));
        }
        #pragma unroll
        for (int i = 0; i < 2; ++i) {
            const int ch = bc0 + 2 * i;
            const float* p = Bp + (size_t)(ch * 8) * LDB + gcol;
            #pragma unroll
            for (int j = 0; j < 8; ++j) fb[i][j] = p[(size_t)j * LDB];
            *(uint4*)&Bs[0][bn][ch * 4] = make_uint4(
                pack_h2(fb[i][0], fb[i][1]), pack_h2(fb[i][2], fb[i][3]),
                pack_h2(fb[i][4], fb[i][5]), pack_h2(fb[i][6], fb[i][7]));
        }
    }
    __syncthreads();

    float accg[2][4][4] = {};
    float accu[2][4][4] = {};

    const int nT = HIDDEN / 32;  // 64
    #pragma unroll 1
    for (int kt = 0; kt < nT; ++kt) {
        const int buf = kt & 1;
        if (kt + 1 < nT) {
            const float* a = Ap + (kt + 1) * 32;
            #pragma unroll
            for (int i = 0; i < 4; ++i)
                ra[i] = *(const float4*)(a + (size_t)(a_row + i * 32) * HIDDEN + a_u * 4);
            #pragma unroll
            for (int i = 0; i < 2; ++i) {
                const int ch = bc0 + 2 * i;
                const float* p = Bp + (size_t)((kt + 1) * 32 + ch * 8) * LDB + gcol;
                #pragma unroll
                for (int j = 0; j < 8; ++j) fb[i][j] = p[(size_t)j * LDB];
            }
        }

        const uint32_t bo = (uint32_t)buf * BUF_BYTES;
        #pragma unroll
        for (int ks = 0; ks < 2; ++ks) {
            const int k8 = ks * 8;
            uint32_t af[2][4];
            #pragma unroll
            for (int im = 0; im < 2; ++im)
                ldsm_x4(af[im][0], af[im][1], af[im][2], af[im][3],
                        As0 + bo + 4u * ((wm + im * 16 + a_lrow) * R_ST + k8 + a_lch));
            uint32_t bg[4][2], bu[4][2];
            ldsm_x4(bg[0][0], bg[0][1], bg[1][0], bg[1][1],
                    Bs0 + bo + 4u * ((wn + b_lcol) * R_ST + k8 + b_lch));
            ldsm_x4(bg[2][0], bg[2][1], bg[3][0], bg[3][1],
                    Bs0 + bo + 4u * ((wn + 16 + b_lcol) * R_ST + k8 + b_lch));
            ldsm_x4(bu[0][0], bu[0][1], bu[1][0], bu[1][1],
                    Bs0 + bo + 4u * ((wn + 64 + b_lcol) * R_ST + k8 + b_lch));
            ldsm_x4(bu[2][0], bu[2][1], bu[3][0], bu[3][1],
                    Bs0 + bo + 4u * ((wn + 80 + b_lcol) * R_ST + k8 + b_lch));
            #pragma unroll
            for (int im = 0; im < 2; ++im) {
                #pragma unroll
                for (int in = 0; in < 4; ++in) {
                    mma_f16(accg[im][in], af[im], bg[in]);
                    mma_f16(accu[im][in], af[im], bu[in]);
                }
            }
        }

        if (kt + 1 < nT) {
            const int nb = (kt + 1) & 1;
            #pragma unroll
            for (int i = 0; i < 4; ++i) {
                const int row = a_row + i * 32;
                *(uint2*)&As[nb][row][a_u * 2] =
                    make_uint2(pack_h2(ra[i].x, ra[i].y), pack_h2(ra[i].z, ra[i].w));
            }
            #pragma unroll
            for (int i = 0; i < 2; ++i) {
                const int ch = bc0 + 2 * i;
                *(uint4*)&Bs[nb][bn][ch * 4] = make_uint4(
                    pack_h2(fb[i][0], fb[i][1]), pack_h2(fb[i][2], fb[i][3]),
                    pack_h2(fb[i][4], fb[i][5]), pack_h2(fb[i][6], fb[i][7]));
            }
        }
        __syncthreads();
    }

    // Epilogue: gated = up * silu(gate) -> Gh32 (fp16x2)
    uint32_t* Gp = Gh32 + (size_t)e * TOKENS * (EXPERT_DIM / 2);
    #pragma unroll
    for (int im = 0; im < 2; ++im) {
        #pragma unroll
        for (int in = 0; in < 4; ++in) {
            #pragma unroll
            for (int h = 0; h < 2; ++h) {
                const int r = m0 + wm + im * 16 + g + h * 8;
                const int c = n0 + wn + in * 8 + 2 * tg;
                const float gv0 = accg[im][in][h * 2 + 0];
                const float gv1 = accg[im][in][h * 2 + 1];
                const float uv0 = accu[im][in][h * 2 + 0];
                const float uv1 = accu[im][in][h * 2 + 1];
                const float s0 = gv0 / (1.0f + __expf(-gv0));
                const float s1 = gv1 / (1.0f + __expf(-gv1));
                Gp[(size_t)r * (EXPERT_DIM / 2) + (c >> 1)] = pack_h2(uv0 * s0, uv1 * s1);
            }
        }
    }
}

// ---------------------------------------------------------------------------
// GEMM2: Out[e] = G[e] (1024x4096 fp16) @ W2[e] (4096x2048 fp32).
// Block 128x128, BK=32 (nT=128). 8 warps = 2(M) x 4(N). Warp tile 64x32.
// 2 CTAs/SM. ldmatrix fragments, 16B B staging.
// ---------------------------------------------------------------------------
__global__ __launch_bounds__(256, 2) void gemm2_kernel(
    const float* __restrict__ W2,   // [E, I, H]
    float* __restrict__ Out)        // [E*T, H]
{
    __shared__ uint32_t As[2][128][R_ST];
    __shared__ uint32_t Bs[2][128][R_ST];

    const int e  = blockIdx.z;
    const int m0 = blockIdx.y * 128;
    const int n0 = blockIdx.x * 128;

    const int tid  = threadIdx.x;
    const int warp = tid >> 5;
    const int lane = tid & 31;
    const int wm = (warp >> 2) * 64;   // 2 warps in M
    const int wn = (warp & 3) * 32;    // 4 warps in N
    const int g  = lane >> 2;
    const int tg = lane & 3;

    const int LDA = EXPERT_DIM / 2;    // words per Gh32 row
    const uint32_t* Ap = Gh32 + (size_t)(e * TOKENS + m0) * LDA;
    const float* Bp = W2 + (size_t)e * EXPERT_DIM * HIDDEN + n0;
    const int LDB = HIDDEN;

    const int a_lrow = lane & 15;
    const int a_lch  = (lane & 16) ? 4 : 0;
    const int b_lcol = (lane & 7) + ((lane & 16) ? 8 : 0);
    const int b_lch  = (lane & 8) ? 4 : 0;
    const uint32_t As0 = smem_u32(&As[0][0][0]);
    const uint32_t Bs0 = smem_u32(&Bs[0][0][0]);

    // A staging: 512 uint4 units (row = idx>>2, q = idx&3), 2/thread
    const int a_row = tid >> 2;
    const int a_q   = tid & 3;
    // B staging: n fixed, chunks {c0, c0+2}
    const int bn  = tid & 127;
    const int bc0 = tid >> 7;

    uint4 ra4[2];
    float fb[2][8];

    {
        #pragma unroll
        for (int i = 0; i < 2; ++i) {
            const int row = a_row + i * 64;
            ra4[i] = *(const uint4*)(Ap + (size_t)row * LDA + a_q * 4);
            *(uint4*)&As[0][row][a_q * 4] = ra4[i];
        }
        #pragma unroll
        for (int i = 0; i < 2; ++i) {
            const int ch = bc0 + 2 * i;
            const float* p = Bp + (size_t)(ch * 8) * LDB + bn;
            #pragma unroll
            for (int j = 0; j < 8; ++j) fb[i][j] = p[(size_t)j * LDB];
            *(uint4*)&Bs[0][bn][ch * 4] = make_uint4(
                pack_h2(fb[i][0], fb[i][1]), pack_h2(fb[i][2], fb[i][3]),
                pack_h2(fb[i][4], fb[i][5]), pack_h2(fb[i][6], fb[i][7]));
        }
    }
    __syncthreads();

    float acc[4][4][4] = {};

    const int nT = EXPERT_DIM / 32;  // 128
    #pragma unroll 1
    for (int kt = 0; kt < nT; ++kt) {
        const int buf = kt & 1;
        if (kt + 1 < nT) {
            #pragma unroll
            for (int i = 0; i < 2; ++i) {
                const int row = a_row + i * 64;
                ra4[i] = *(const uint4*)(Ap + (size_t)row * LDA + (kt + 1) * 16 + a_q * 4);
            }
            #pragma unroll
            for (int i = 0; i < 2; ++i) {
                const int ch = bc0 + 2 * i;
                const float* p = Bp + (size_t)((kt + 1) * 32 + ch * 8) * LDB + bn;
                #pragma unroll
                for (int j = 0; j < 8; ++j) fb[i][j] = p[(size_t)j * LDB];
            }
        }

        const uint32_t bo = (uint32_t)buf * BUF_BYTES;
        #pragma unroll
        for (int ks = 0; ks < 2; ++ks) {
            const int k8 = ks * 8;
            uint32_t af[4][4];
            #pragma unroll
            for (int im = 0; im < 4; ++im)
                ldsm_x4(af[im][0], af[im][1], af[im][2], af[im][3],
                        As0 + bo + 4u * ((wm + im * 16 + a_lrow) * R_ST + k8 + a_lch));
            uint32_t bf[4][2];
            ldsm_x4(bf[0][0], bf[0][1], bf[1][0], bf[1][1],
                    Bs0 + bo + 4u * ((wn + b_lcol) * R_ST + k8 + b_lch));
            ldsm_x4(bf[2][0], bf[2][1], bf[3][0], bf[3][1],
                    Bs0 + bo + 4u * ((wn + 16 + b_lcol) * R_ST + k8 + b_lch));
            #pragma unroll
            for (int im = 0; im < 4; ++im) {
                #pragma unroll
                for (int in = 0; in < 4; ++in) {
                    mma_f16(acc[im][in], af[im], bf[in]);
                }
            }
        }

        if (kt + 1 < nT) {
            const int nb = (kt + 1) & 1;
            #pragma unroll
            for (int i = 0; i < 2; ++i) {
                const int row = a_row + i * 64;
                *(uint4*)&As[nb][row][a_q * 4] = ra4[i];
            }
            #pragma unroll
            for (int i = 0; i < 2; ++i) {
                const int ch = bc0 + 2 * i;
                *(uint4*)&Bs[nb][bn][ch * 4] = make_uint4(
                    pack_h2(fb[i][0], fb[i][1]), pack_h2(fb[i][2], fb[i][3]),
                    pack_h2(fb[i][4], fb[i][5]), pack_h2(fb[i][6], fb[i][7]));
            }
        }
        __syncthreads();
    }

    float* Optr = Out + (size_t)(e * TOKENS + m0) * HIDDEN + n0;
    #pragma unroll
    for (int im = 0; im < 4; ++im) {
        #pragma unroll
        for (int in = 0; in < 4; ++in) {
            #pragma unroll
            for (int h = 0; h < 2; ++h) {
                const int r = wm + im * 16 + g + h * 8;
                const int c = wn + in * 8 + 2 * tg;
                *(float2*)(Optr + (size_t)r * HIDDEN + c) =
                    make_float2(acc[im][in][h * 2 + 0], acc[im][in][h * 2 + 1]);
            }
        }
    }
}

extern "C" void kernel_launch(void* const* d_in, const int* in_sizes, int n_in,
                              void* d_out, int out_size) {
    const float* X  = (const float*)d_in[0];   // hidden_states [8192, 2048]
    const float* W1 = (const float*)d_in[1];   // gate_up_proj  [8, 2048, 8192]
    const float* W2 = (const float*)d_in[2];   // down_proj     [8, 4096, 2048]
    float* Out = (float*)d_out;                // [8192, 2048]

    dim3 blk(256);
    dim3 g1(EXPERT_DIM / 64, TOKENS / 128, NUM_EXPERTS);   // 64 x 8 x 8
    dim3 g2(HIDDEN / 128, TOKENS / 128, NUM_EXPERTS);      // 16 x 8 x 8
    gemm1_kernel<<<g1, blk>>>(X, W1);
    gemm2_kernel<<<g2, blk>>>(W2, Out);
}